// round 5
// baseline (speedup 1.0000x reference)
#include <cuda_runtime.h>
#include <math.h>

// Fused: conv3d(32->64, k=3, pad=1) + bias + maxpool(2,2,2) + logsumexp(ch) + relu
// x: [16,32,48,48,48]  w: [64,32,3,3,3]  b: [64]  out: [16,1,24,24,24]
//
// Grid: (216 tiles, 16 batches). Block: 512 threads = 64 pooled cells x 8 oc-groups.
// Each CTA computes an 8x8x8 conv tile (=4x4x4 pooled cells), all 64 channels,
// looping over 32 input channels with smem-staged input halo (10^3) + weights.
// Accumulation uses packed fp32x2 FMA (fma.rn.f32x2) over output-channel pairs.

#define IN_PY 12     // padded y-stride (floats)
#define IN_PZ 120    // padded z-stride (floats)

__global__ void __launch_bounds__(512, 1)
fused_conv_pool_lse_kernel(const float* __restrict__ x,
                           const float* __restrict__ w,
                           const float* __restrict__ b,
                           float* __restrict__ out)
{
    __shared__ __align__(16) float in_s[10 * IN_PZ];          // 10x10x10 halo, padded
    __shared__ __align__(16) float w_s[32 * 27 * 2];          // [oc_pair][k][half]
    __shared__ float b_s[64];
    __shared__ float red_max[64 * 8];
    __shared__ float red_sum[64 * 8];

    const int n  = blockIdx.y;
    const int t  = blockIdx.x;                 // 0..215
    const int tz = t / 36;
    const int ty = (t / 6) % 6;
    const int tx = t % 6;
    const int d0 = tz * 8, h0 = ty * 8, w0 = tx * 8;   // conv-tile origin

    const int tid  = threadIdx.x;
    const int cell = tid & 63;                 // pooled cell within 4x4x4
    const int ocg  = tid >> 6;                 // oc group 0..7 (8 oc each)
    const int cx = cell & 3, cy = (cell >> 2) & 3, cz = cell >> 4;

    if (tid < 64) b_s[tid] = b[tid];

    // acc[pos][pair]: pos = dz*4+dy*2+dx over the 2x2x2 pooling window,
    // pair = packed (oc0, oc1) fp32x2 accumulator.
    unsigned long long acc[8][4];
#pragma unroll
    for (int i = 0; i < 8; ++i)
#pragma unroll
        for (int j = 0; j < 4; ++j) acc[i][j] = 0ull;

    const float* xn = x + (size_t)n * 32 * 48 * 48 * 48;

    for (int ic = 0; ic < 32; ++ic) {
        __syncthreads();   // protect smem from previous iteration's readers

        // ---- stage input halo slice [d0-1 .. d0+8]^3 (zero padded) ----
        const float* xc = xn + (size_t)ic * 48 * 48 * 48;
#pragma unroll
        for (int i = 0; i < 2; ++i) {
            int idx = tid + i * 512;
            if (idx < 1000) {
                int zi  = idx / 100;
                int rem = idx - zi * 100;
                int yi  = rem / 10;
                int xi  = rem - yi * 10;
                int gz = d0 - 1 + zi, gy = h0 - 1 + yi, gx = w0 - 1 + xi;
                float v = 0.0f;
                if ((unsigned)gz < 48u && (unsigned)gy < 48u && (unsigned)gx < 48u)
                    v = xc[(gz * 48 + gy) * 48 + gx];
                in_s[zi * IN_PZ + yi * IN_PY + xi] = v;
            }
        }

        // ---- stage weights for this ic: 64 oc x 27, pair-interleaved ----
        const float* wc = w + (size_t)ic * 27;
#pragma unroll
        for (int i = 0; i < 4; ++i) {
            int idx = tid + i * 512;
            if (idx < 1728) {
                int oc = idx / 27;
                int k  = idx - oc * 27;
                float v = wc[(size_t)oc * (32 * 27) + k];
                w_s[((oc >> 1) * 27 + k) * 2 + (oc & 1)] = v;
            }
        }
        __syncthreads();

        // ---- accumulate ----
        const float* inb = in_s + (2 * cz) * IN_PZ + (2 * cy) * IN_PY + 2 * cx;
        const float* wb  = w_s + (ocg * 4) * 27 * 2;

#pragma unroll
        for (int kz = 0; kz < 3; ++kz) {
#pragma unroll
            for (int ky = 0; ky < 3; ++ky) {
                // hoist weight pairs for kx = 0..2 (warp-uniform -> smem broadcast)
                unsigned long long wq[3][4];
#pragma unroll
                for (int kx = 0; kx < 3; ++kx) {
                    const int k = (kz * 3 + ky) * 3 + kx;
#pragma unroll
                    for (int pr = 0; pr < 4; ++pr)
                        wq[kx][pr] = *(const unsigned long long*)(wb + (pr * 27 + k) * 2);
                }
#pragma unroll
                for (int dz = 0; dz < 2; ++dz) {
#pragma unroll
                    for (int dy = 0; dy < 2; ++dy) {
                        const float* row = inb + (dz + kz) * IN_PZ + (dy + ky) * IN_PY;
                        // 4 consecutive x values cover all kx+dx combinations
                        float2 v01 = *(const float2*)(row);
                        float2 v23 = *(const float2*)(row + 2);
                        float vv[4];
                        vv[0] = v01.x; vv[1] = v01.y; vv[2] = v23.x; vv[3] = v23.y;
                        unsigned long long pdup[4];
#pragma unroll
                        for (int q = 0; q < 4; ++q)
                            asm("mov.b64 %0, {%1, %1};"
                                : "=l"(pdup[q]) : "r"(__float_as_uint(vv[q])));
#pragma unroll
                        for (int kx = 0; kx < 3; ++kx) {
#pragma unroll
                            for (int dx = 0; dx < 2; ++dx) {
                                const int pos = dz * 4 + dy * 2 + dx;
#pragma unroll
                                for (int pr = 0; pr < 4; ++pr)
                                    asm("fma.rn.f32x2 %0, %1, %2, %0;"
                                        : "+l"(acc[pos][pr])
                                        : "l"(pdup[kx + dx]), "l"(wq[kx][pr]));
                            }
                        }
                    }
                }
            }
        }
    }

    // ---- epilogue: bias + maxpool (in registers) ----
    float m[8];
#pragma unroll
    for (int pr = 0; pr < 4; ++pr) {
        float m0 = -INFINITY, m1 = -INFINITY;
#pragma unroll
        for (int pos = 0; pos < 8; ++pos) {
            unsigned int lo, hi;
            asm("mov.b64 {%0, %1}, %2;" : "=r"(lo), "=r"(hi) : "l"(acc[pos][pr]));
            m0 = fmaxf(m0, __uint_as_float(lo));
            m1 = fmaxf(m1, __uint_as_float(hi));
        }
        const int oc0 = ocg * 8 + pr * 2;
        m[pr * 2]     = m0 + b_s[oc0];
        m[pr * 2 + 1] = m1 + b_s[oc0 + 1];
    }
    float mx = m[0];
#pragma unroll
    for (int i = 1; i < 8; ++i) mx = fmaxf(mx, m[i]);

    // ---- logsumexp across the 8 oc-groups of this cell ----
    __syncthreads();
    red_max[cell * 8 + ocg] = mx;
    __syncthreads();

    float M = red_max[cell * 8 + 0];
#pragma unroll
    for (int i = 1; i < 8; ++i) M = fmaxf(M, red_max[cell * 8 + i]);

    float s = 0.0f;
#pragma unroll
    for (int i = 0; i < 8; ++i) s += expf(m[i] - M);
    red_sum[cell * 8 + ocg] = s;
    __syncthreads();

    if (ocg == 0) {
        float S = 0.0f;
#pragma unroll
        for (int i = 0; i < 8; ++i) S += red_sum[cell * 8 + i];
        float lse = M + logf(S);
        lse = fmaxf(lse, 0.0f);
        const int pd = tz * 4 + cz;
        const int ph = ty * 4 + cy;
        const int pw = tx * 4 + cx;
        out[((n * 24 + pd) * 24 + ph) * 24 + pw] = lse;
    }
}

extern "C" void kernel_launch(void* const* d_in, const int* in_sizes, int n_in,
                              void* d_out, int out_size)
{
    const float* x = (const float*)d_in[0];
    const float* w = (const float*)d_in[1];
    const float* b = (const float*)d_in[2];
    float* out = (float*)d_out;

    dim3 grid(216, 16);   // 6*6*6 conv tiles per batch, 16 batches
    fused_conv_pool_lse_kernel<<<grid, 512>>>(x, w, b, out);
}

// round 6
// speedup vs baseline: 1.0035x; 1.0035x over previous
#include <cuda_runtime.h>
#include <math.h>

// Fused: conv3d(32->64, k=3, pad=1) + bias + maxpool(2,2,2) + logsumexp(ch) + relu
// x: [16,32,48,48,48]  w: [64,32,3,3,3]  b: [64]  out: [16,1,24,24,24]
//
// Grid: (216 tiles, 16 batches). Block: 512 threads = 64 pooled cells x 8 oc-groups.
// Each CTA computes an 8x8x8 conv tile (=4x4x4 pooled cells), all 64 channels,
// looping over 32 input channels with smem-staged input halo (10^3) + weights.
// Accumulation uses packed fp32x2 FMA (fma.rn.f32x2) over output-channel pairs.

#define IN_PY 12     // padded y-stride (floats)
#define IN_PZ 120    // padded z-stride (floats)

__global__ void __launch_bounds__(512, 1)
fused_conv_pool_lse_kernel(const float* __restrict__ x,
                           const float* __restrict__ w,
                           const float* __restrict__ b,
                           float* __restrict__ out)
{
    __shared__ __align__(16) float in_s[10 * IN_PZ];          // 10x10x10 halo, padded
    __shared__ __align__(16) float w_s[32 * 27 * 2];          // [oc_pair][k][half]
    __shared__ float b_s[64];
    __shared__ float red_max[64 * 8];
    __shared__ float red_sum[64 * 8];

    const int n  = blockIdx.y;
    const int t  = blockIdx.x;                 // 0..215
    const int tz = t / 36;
    const int ty = (t / 6) % 6;
    const int tx = t % 6;
    const int d0 = tz * 8, h0 = ty * 8, w0 = tx * 8;   // conv-tile origin

    const int tid  = threadIdx.x;
    const int cell = tid & 63;                 // pooled cell within 4x4x4
    const int ocg  = tid >> 6;                 // oc group 0..7 (8 oc each)
    const int cx = cell & 3, cy = (cell >> 2) & 3, cz = cell >> 4;

    if (tid < 64) b_s[tid] = b[tid];

    // acc[pos][pair]: pos = dz*4+dy*2+dx over the 2x2x2 pooling window,
    // pair = packed (oc0, oc1) fp32x2 accumulator.
    unsigned long long acc[8][4];
#pragma unroll
    for (int i = 0; i < 8; ++i)
#pragma unroll
        for (int j = 0; j < 4; ++j) acc[i][j] = 0ull;

    const float* xn = x + (size_t)n * 32 * 48 * 48 * 48;

    for (int ic = 0; ic < 32; ++ic) {
        __syncthreads();   // protect smem from previous iteration's readers

        // ---- stage input halo slice [d0-1 .. d0+8]^3 (zero padded) ----
        const float* xc = xn + (size_t)ic * 48 * 48 * 48;
#pragma unroll
        for (int i = 0; i < 2; ++i) {
            int idx = tid + i * 512;
            if (idx < 1000) {
                int zi  = idx / 100;
                int rem = idx - zi * 100;
                int yi  = rem / 10;
                int xi  = rem - yi * 10;
                int gz = d0 - 1 + zi, gy = h0 - 1 + yi, gx = w0 - 1 + xi;
                float v = 0.0f;
                if ((unsigned)gz < 48u && (unsigned)gy < 48u && (unsigned)gx < 48u)
                    v = xc[(gz * 48 + gy) * 48 + gx];
                in_s[zi * IN_PZ + yi * IN_PY + xi] = v;
            }
        }

        // ---- stage weights for this ic: 64 oc x 27, pair-interleaved ----
        const float* wc = w + (size_t)ic * 27;
#pragma unroll
        for (int i = 0; i < 4; ++i) {
            int idx = tid + i * 512;
            if (idx < 1728) {
                int oc = idx / 27;
                int k  = idx - oc * 27;
                float v = wc[(size_t)oc * (32 * 27) + k];
                w_s[((oc >> 1) * 27 + k) * 2 + (oc & 1)] = v;
            }
        }
        __syncthreads();

        // ---- accumulate ----
        const float* inb = in_s + (2 * cz) * IN_PZ + (2 * cy) * IN_PY + 2 * cx;
        const float* wb  = w_s + (ocg * 4) * 27 * 2;

#pragma unroll
        for (int kz = 0; kz < 3; ++kz) {
#pragma unroll
            for (int ky = 0; ky < 3; ++ky) {
                // hoist weight pairs for kx = 0..2 (warp-uniform -> smem broadcast)
                unsigned long long wq[3][4];
#pragma unroll
                for (int kx = 0; kx < 3; ++kx) {
                    const int k = (kz * 3 + ky) * 3 + kx;
#pragma unroll
                    for (int pr = 0; pr < 4; ++pr)
                        wq[kx][pr] = *(const unsigned long long*)(wb + (pr * 27 + k) * 2);
                }
#pragma unroll
                for (int dz = 0; dz < 2; ++dz) {
#pragma unroll
                    for (int dy = 0; dy < 2; ++dy) {
                        const float* row = inb + (dz + kz) * IN_PZ + (dy + ky) * IN_PY;
                        // 4 consecutive x values cover all kx+dx combinations
                        float2 v01 = *(const float2*)(row);
                        float2 v23 = *(const float2*)(row + 2);
                        float vv[4];
                        vv[0] = v01.x; vv[1] = v01.y; vv[2] = v23.x; vv[3] = v23.y;
                        unsigned long long pdup[4];
#pragma unroll
                        for (int q = 0; q < 4; ++q)
                            asm("mov.b64 %0, {%1, %1};"
                                : "=l"(pdup[q]) : "r"(__float_as_uint(vv[q])));
#pragma unroll
                        for (int kx = 0; kx < 3; ++kx) {
#pragma unroll
                            for (int dx = 0; dx < 2; ++dx) {
                                const int pos = dz * 4 + dy * 2 + dx;
#pragma unroll
                                for (int pr = 0; pr < 4; ++pr)
                                    asm("fma.rn.f32x2 %0, %1, %2, %0;"
                                        : "+l"(acc[pos][pr])
                                        : "l"(pdup[kx + dx]), "l"(wq[kx][pr]));
                            }
                        }
                    }
                }
            }
        }
    }

    // ---- epilogue: bias + maxpool (in registers) ----
    float m[8];
#pragma unroll
    for (int pr = 0; pr < 4; ++pr) {
        float m0 = -INFINITY, m1 = -INFINITY;
#pragma unroll
        for (int pos = 0; pos < 8; ++pos) {
            unsigned int lo, hi;
            asm("mov.b64 {%0, %1}, %2;" : "=r"(lo), "=r"(hi) : "l"(acc[pos][pr]));
            m0 = fmaxf(m0, __uint_as_float(lo));
            m1 = fmaxf(m1, __uint_as_float(hi));
        }
        const int oc0 = ocg * 8 + pr * 2;
        m[pr * 2]     = m0 + b_s[oc0];
        m[pr * 2 + 1] = m1 + b_s[oc0 + 1];
    }
    float mx = m[0];
#pragma unroll
    for (int i = 1; i < 8; ++i) mx = fmaxf(mx, m[i]);

    // ---- logsumexp across the 8 oc-groups of this cell ----
    __syncthreads();
    red_max[cell * 8 + ocg] = mx;
    __syncthreads();

    float M = red_max[cell * 8 + 0];
#pragma unroll
    for (int i = 1; i < 8; ++i) M = fmaxf(M, red_max[cell * 8 + i]);

    float s = 0.0f;
#pragma unroll
    for (int i = 0; i < 8; ++i) s += expf(m[i] - M);
    red_sum[cell * 8 + ocg] = s;
    __syncthreads();

    if (ocg == 0) {
        float S = 0.0f;
#pragma unroll
        for (int i = 0; i < 8; ++i) S += red_sum[cell * 8 + i];
        float lse = M + logf(S);
        lse = fmaxf(lse, 0.0f);
        const int pd = tz * 4 + cz;
        const int ph = ty * 4 + cy;
        const int pw = tx * 4 + cx;
        out[((n * 24 + pd) * 24 + ph) * 24 + pw] = lse;
    }
}

extern "C" void kernel_launch(void* const* d_in, const int* in_sizes, int n_in,
                              void* d_out, int out_size)
{
    const float* x = (const float*)d_in[0];
    const float* w = (const float*)d_in[1];
    const float* b = (const float*)d_in[2];
    float* out = (float*)d_out;

    dim3 grid(216, 16);   // 6*6*6 conv tiles per batch, 16 batches
    fused_conv_pool_lse_kernel<<<grid, 512>>>(x, w, b, out);
}